// round 15
// baseline (speedup 1.0000x reference)
#include <cuda_runtime.h>
#include <cuda_fp16.h>
#include <math.h>

#define N_NODES 100000
#define N_EDGES 1000000
#define N_GRAPHS 128
#define HD 64
#define BN_EPS 1e-5f

#define SCAN_BLK 25            // ceil(100000 / 4096)

// ---------------- scratch (device globals; no allocation allowed) ----------------
__device__ __align__(16) int    g_rowptr[N_NODES + 1];
__device__ __align__(16) int    g_cursor[N_NODES];
__device__ __align__(16) int    g_deg[N_NODES];
__device__ __align__(16) int    g_bsum[SCAN_BLK];
__device__ __align__(16) int    g_csrsrc[N_EDGES];
__device__ __align__(16) __half g_y[N_NODES * HD];
__device__ __align__(16) __half g_a[N_NODES * HD];
__device__ __align__(16) __half g_wt[7 * 4096];   // fp16 W^T [n][k], 7 matrices
__device__ __align__(16) float  g_pool[N_GRAPHS * HD];
__device__ __align__(16) int    g_cnt[N_GRAPHS];

// ---------------- helpers ----------------
__device__ __forceinline__ unsigned f2tf(float f) {
    unsigned u;
    asm("cvt.rna.tf32.f32 %0, %1;" : "=r"(u) : "f"(f));
    return u;
}
__device__ __forceinline__ void mma_tf32(float* c, const unsigned* a,
                                         unsigned b0, unsigned b1) {
    asm("mma.sync.aligned.m16n8k8.row.col.f32.tf32.tf32.f32 "
        "{%0,%1,%2,%3},{%4,%5,%6,%7},{%8,%9},{%0,%1,%2,%3};"
        : "+f"(c[0]), "+f"(c[1]), "+f"(c[2]), "+f"(c[3])
        : "r"(a[0]), "r"(a[1]), "r"(a[2]), "r"(a[3]), "r"(b0), "r"(b1));
}
__device__ __forceinline__ void mma_f16(float* c, const unsigned* a,
                                        unsigned b0, unsigned b1) {
    asm("mma.sync.aligned.m16n8k16.row.col.f32.f16.f16.f32 "
        "{%0,%1,%2,%3},{%4,%5,%6,%7},{%8,%9},{%0,%1,%2,%3};"
        : "+f"(c[0]), "+f"(c[1]), "+f"(c[2]), "+f"(c[3])
        : "r"(a[0]), "r"(a[1]), "r"(a[2]), "r"(a[3]), "r"(b0), "r"(b1));
}

// ---------------- weight prep: fp16 transposed copies (overlapped) ----------------
__global__ void k_wprep(const float* __restrict__ W2_0,
                        const float* __restrict__ W1_r,
                        const float* __restrict__ W2_r) {
    int b = blockIdx.x;
    const float* src = (b == 0) ? W2_0
                     : ((b & 1) ? W1_r + ((b - 1) / 2) * 4096
                                : W2_r + (b / 2 - 1) * 4096);
    __half* dst = g_wt + b * 4096;
    for (int i = threadIdx.x; i < 4096; i += 256) {
        int n = i >> 6, k = i & 63;
        dst[i] = __float2half(src[k * 64 + n]);
    }
}

// ---------------- CSR build ----------------
__global__ void k_count(const int* __restrict__ ei,
                        const int* __restrict__ batch) {
    int e = (blockIdx.x * blockDim.x + threadIdx.x) * 4;
    if (e < N_EDGES) {
        int4 d = *(const int4*)&ei[N_EDGES + e];
        atomicAdd(&g_deg[d.x], 1);
        atomicAdd(&g_deg[d.y], 1);
        atomicAdd(&g_deg[d.z], 1);
        atomicAdd(&g_deg[d.w], 1);
    }
    if (e < N_NODES) {
        int4 b = *(const int4*)&batch[e];
        atomicAdd(&g_cnt[b.x], 1);
        atomicAdd(&g_cnt[b.y], 1);
        atomicAdd(&g_cnt[b.z], 1);
        atomicAdd(&g_cnt[b.w], 1);
    }
}

__global__ __launch_bounds__(1024) void k_scan1() {
    __shared__ int warpsum[32];
    int tid = threadIdx.x, lane = tid & 31, wid = tid >> 5;
    int i0 = blockIdx.x * 4096 + tid * 4;
    int4 v = make_int4(0, 0, 0, 0);
    if (i0 + 3 < N_NODES) {
        v = *(const int4*)&g_deg[i0];
    } else {
        if (i0 + 0 < N_NODES) v.x = g_deg[i0 + 0];
        if (i0 + 1 < N_NODES) v.y = g_deg[i0 + 1];
        if (i0 + 2 < N_NODES) v.z = g_deg[i0 + 2];
        if (i0 + 3 < N_NODES) v.w = g_deg[i0 + 3];
    }
    int s = v.x + v.y + v.z + v.w;
    int x = s;
    #pragma unroll
    for (int off = 1; off < 32; off <<= 1) {
        int t = __shfl_up_sync(0xffffffffu, x, off);
        if (lane >= off) x += t;
    }
    if (lane == 31) warpsum[wid] = x;
    __syncthreads();
    if (wid == 0) {
        int w = warpsum[lane];
        #pragma unroll
        for (int off = 1; off < 32; off <<= 1) {
            int t = __shfl_up_sync(0xffffffffu, w, off);
            if (lane >= off) w += t;
        }
        warpsum[lane] = w;
    }
    __syncthreads();
    int woff = (wid > 0) ? warpsum[wid - 1] : 0;
    int excl = woff + (x - s);
    int p0 = excl + v.x, p1 = p0 + v.y, p2 = p1 + v.z;
    if (i0 + 0 < N_NODES) g_cursor[i0 + 0] = excl;
    if (i0 + 1 < N_NODES) g_cursor[i0 + 1] = p0;
    if (i0 + 2 < N_NODES) g_cursor[i0 + 2] = p1;
    if (i0 + 3 < N_NODES) g_cursor[i0 + 3] = p2;
    if (tid == 1023) g_bsum[blockIdx.x] = warpsum[31];
}

__global__ __launch_bounds__(1024) void k_scan23() {
    __shared__ int s_off;
    int tid = threadIdx.x;
    if (tid < 32) {
        int lane = tid;
        int v = (lane < SCAN_BLK) ? g_bsum[lane] : 0;
        int x = v;
        #pragma unroll
        for (int off = 1; off < 32; off <<= 1) {
            int t = __shfl_up_sync(0xffffffffu, x, off);
            if (lane >= off) x += t;
        }
        if (lane == blockIdx.x) s_off = x - v;
    }
    __syncthreads();
    int off = s_off;
    int i0 = blockIdx.x * 4096 + tid * 4;
    if (i0 + 3 < N_NODES) {
        int4 c = *(const int4*)&g_cursor[i0];
        c.x += off; c.y += off; c.z += off; c.w += off;
        *(int4*)&g_cursor[i0] = c;
        *(int4*)&g_rowptr[i0] = c;
        *(int4*)&g_deg[i0] = make_int4(0, 0, 0, 0);
    } else {
        #pragma unroll
        for (int j = 0; j < 4; j++) {
            if (i0 + j < N_NODES) {
                int c = g_cursor[i0 + j] + off;
                g_cursor[i0 + j] = c;
                g_rowptr[i0 + j] = c;
                g_deg[i0 + j] = 0;
            }
        }
    }
    if (blockIdx.x == 0 && tid == 0) g_rowptr[N_NODES] = N_EDGES;
}

__global__ void k_scatter(const int* __restrict__ ei) {
    int e = (blockIdx.x * blockDim.x + threadIdx.x) * 4;
    if (e >= N_EDGES) return;
    int4 d = *(const int4*)&ei[N_EDGES + e];
    int4 s = *(const int4*)&ei[e];
    int p0 = atomicAdd(&g_cursor[d.x], 1);
    int p1 = atomicAdd(&g_cursor[d.y], 1);
    int p2 = atomicAdd(&g_cursor[d.z], 1);
    int p3 = atomicAdd(&g_cursor[d.w], 1);
    g_csrsrc[p0] = s.x;
    g_csrsrc[p1] = s.y;
    g_csrsrc[p2] = s.z;
    g_csrsrc[p3] = s.w;
}

// ---------------- layer-0 input GEMM: g_y = x[N,128] @ W1_0[128,64] (TF32) ----
__global__ __launch_bounds__(256) void k_gemm0(const float* __restrict__ A,
                                               const float* __restrict__ W) {
    constexpr int K = 128;
    __shared__ unsigned sA[256 * 17];
    __shared__ unsigned sW[16 * 65];
    int tid = threadIdx.x;
    int wid = tid >> 5, lane = tid & 31;
    int tg = lane >> 2, tig = lane & 3;
    int row0 = blockIdx.x * 256;

    float c[2][8][4];
    #pragma unroll
    for (int mt = 0; mt < 2; mt++)
        #pragma unroll
        for (int nt = 0; nt < 8; nt++)
            #pragma unroll
            for (int j = 0; j < 4; j++) c[mt][nt][j] = 0.f;

    for (int ch = 0; ch < 8; ch++) {
        int kbase = ch * 16;
        #pragma unroll
        for (int i = 0; i < 4; i++) {
            int idx = tid + i * 256;
            int r = idx >> 2, c4 = idx & 3;
            int grow = row0 + r;
            float4 v = make_float4(0.f, 0.f, 0.f, 0.f);
            if (grow < N_NODES)
                v = *(const float4*)(A + (size_t)grow * K + kbase + c4 * 4);
            unsigned* p = &sA[r * 17 + c4 * 4];
            p[0] = f2tf(v.x); p[1] = f2tf(v.y); p[2] = f2tf(v.z); p[3] = f2tf(v.w);
        }
        {
            int k = tid >> 4, c4 = tid & 15;
            float4 v = *(const float4*)(W + (size_t)(kbase + k) * 64 + c4 * 4);
            unsigned* p = &sW[k * 65 + c4 * 4];
            p[0] = f2tf(v.x); p[1] = f2tf(v.y); p[2] = f2tf(v.z); p[3] = f2tf(v.w);
        }
        __syncthreads();
        #pragma unroll
        for (int ks = 0; ks < 2; ks++) {
            int ko = ks * 8;
            unsigned a[2][4];
            #pragma unroll
            for (int mt = 0; mt < 2; mt++) {
                int rr = wid * 32 + mt * 16 + tg;
                a[mt][0] = sA[rr * 17 + ko + tig];
                a[mt][1] = sA[(rr + 8) * 17 + ko + tig];
                a[mt][2] = sA[rr * 17 + ko + tig + 4];
                a[mt][3] = sA[(rr + 8) * 17 + ko + tig + 4];
            }
            #pragma unroll
            for (int nt = 0; nt < 8; nt++) {
                unsigned b0 = sW[(ko + tig) * 65 + nt * 8 + tg];
                unsigned b1 = sW[(ko + tig + 4) * 65 + nt * 8 + tg];
                mma_tf32(c[0][nt], a[0], b0, b1);
                mma_tf32(c[1][nt], a[1], b0, b1);
            }
        }
        __syncthreads();
    }
    #pragma unroll
    for (int mt = 0; mt < 2; mt++) {
        int row = row0 + wid * 32 + mt * 16 + tg;
        #pragma unroll
        for (int half_i = 0; half_i < 2; half_i++) {
            int r = row + half_i * 8;
            if (r < N_NODES) {
                #pragma unroll
                for (int nt = 0; nt < 8; nt++) {
                    int col = nt * 8 + tig * 2;
                    *(__half2*)(g_y + (size_t)r * HD + col) =
                        __float22half2_rn(make_float2(c[mt][nt][half_i * 2 + 0],
                                                      c[mt][nt][half_i * 2 + 1]));
                }
            }
        }
    }
}

// ---------------- chained dual GEMM, fp16 MMA, pre-transposed weights ----------
template <bool DUAL>
__global__ __launch_bounds__(128) void k_dual(int slot2, int slot1,
                                              const int* __restrict__ batch) {
    __shared__ __half sA[128 * 72];
    __shared__ __half sW2[64 * 72];
    __shared__ __half sW1[64 * 72];

    const __half* WT2 = g_wt + slot2 * 4096;
    const __half* WT1n = g_wt + slot1 * 4096;

    int tid = threadIdx.x, wid = tid >> 5, lane = tid & 31;
    int tg = lane >> 2, tig = lane & 3;
    int row0 = blockIdx.x * 128;

    #pragma unroll
    for (int i = 0; i < 8; i++) {
        int idx = tid + i * 128;
        int r = idx >> 3, seg = idx & 7;
        int grow = row0 + r;
        uint4 raw = make_uint4(0u, 0u, 0u, 0u);
        if (grow < N_NODES)
            raw = *(const uint4*)(g_a + (size_t)grow * HD + seg * 8);
        *(uint4*)&sA[r * 72 + seg * 8] = raw;
    }
    #pragma unroll
    for (int i = 0; i < 4; i++) {
        int idx = tid + i * 128;
        int r = idx >> 3, seg = idx & 7;
        *(uint4*)&sW2[r * 72 + seg * 8] = *(const uint4*)(WT2 + r * 64 + seg * 8);
        if (DUAL)
            *(uint4*)&sW1[r * 72 + seg * 8] = *(const uint4*)(WT1n + r * 64 + seg * 8);
    }
    __syncthreads();

    float c[2][8][4];
    #pragma unroll
    for (int mt = 0; mt < 2; mt++)
        #pragma unroll
        for (int nt = 0; nt < 8; nt++)
            #pragma unroll
            for (int j = 0; j < 4; j++) c[mt][nt][j] = 0.f;

    #pragma unroll
    for (int ks = 0; ks < 4; ks++) {
        int kg = ks * 16;
        unsigned a[2][4];
        #pragma unroll
        for (int mt = 0; mt < 2; mt++) {
            int rr = wid * 32 + mt * 16 + tg;
            a[mt][0] = *(unsigned*)&sA[rr * 72 + kg + 2 * tig];
            a[mt][1] = *(unsigned*)&sA[(rr + 8) * 72 + kg + 2 * tig];
            a[mt][2] = *(unsigned*)&sA[rr * 72 + kg + 2 * tig + 8];
            a[mt][3] = *(unsigned*)&sA[(rr + 8) * 72 + kg + 2 * tig + 8];
        }
        #pragma unroll
        for (int nt = 0; nt < 8; nt++) {
            unsigned b0 = *(unsigned*)&sW2[(nt * 8 + tg) * 72 + kg + 2 * tig];
            unsigned b1 = *(unsigned*)&sW2[(nt * 8 + tg) * 72 + kg + 2 * tig + 8];
            mma_f16(c[0][nt], a[0], b0, b1);
            mma_f16(c[1][nt], a[1], b0, b1);
        }
    }

    if (!DUAL) {
        #pragma unroll
        for (int mt = 0; mt < 2; mt++) {
            int row = row0 + wid * 32 + mt * 16 + tg;
            #pragma unroll
            for (int half_i = 0; half_i < 2; half_i++) {
                int r = row + half_i * 8;
                if (r < N_NODES) {
                    int b = batch[r];
                    #pragma unroll
                    for (int nt = 0; nt < 8; nt++) {
                        int col = nt * 8 + tig * 2;
                        atomicAdd(&g_pool[b * HD + col],
                                  fmaxf(c[mt][nt][half_i * 2 + 0], 0.f));
                        atomicAdd(&g_pool[b * HD + col + 1],
                                  fmaxf(c[mt][nt][half_i * 2 + 1], 0.f));
                    }
                }
            }
        }
        return;
    }

    #pragma unroll
    for (int mt = 0; mt < 2; mt++) {
        int rlo = wid * 32 + mt * 16 + tg;
        #pragma unroll
        for (int nt = 0; nt < 8; nt++) {
            int col = nt * 8 + 2 * tig;
            *(__half2*)&sA[rlo * 72 + col] =
                __float22half2_rn(make_float2(fmaxf(c[mt][nt][0], 0.f),
                                              fmaxf(c[mt][nt][1], 0.f)));
            *(__half2*)&sA[(rlo + 8) * 72 + col] =
                __float22half2_rn(make_float2(fmaxf(c[mt][nt][2], 0.f),
                                              fmaxf(c[mt][nt][3], 0.f)));
        }
    }
    __syncwarp();

    #pragma unroll
    for (int mt = 0; mt < 2; mt++)
        #pragma unroll
        for (int nt = 0; nt < 8; nt++)
            #pragma unroll
            for (int j = 0; j < 4; j++) c[mt][nt][j] = 0.f;

    #pragma unroll
    for (int ks = 0; ks < 4; ks++) {
        int kg = ks * 16;
        unsigned a[2][4];
        #pragma unroll
        for (int mt = 0; mt < 2; mt++) {
            int rr = wid * 32 + mt * 16 + tg;
            a[mt][0] = *(unsigned*)&sA[rr * 72 + kg + 2 * tig];
            a[mt][1] = *(unsigned*)&sA[(rr + 8) * 72 + kg + 2 * tig];
            a[mt][2] = *(unsigned*)&sA[rr * 72 + kg + 2 * tig + 8];
            a[mt][3] = *(unsigned*)&sA[(rr + 8) * 72 + kg + 2 * tig + 8];
        }
        #pragma unroll
        for (int nt = 0; nt < 8; nt++) {
            unsigned b0 = *(unsigned*)&sW1[(nt * 8 + tg) * 72 + kg + 2 * tig];
            unsigned b1 = *(unsigned*)&sW1[(nt * 8 + tg) * 72 + kg + 2 * tig + 8];
            mma_f16(c[0][nt], a[0], b0, b1);
            mma_f16(c[1][nt], a[1], b0, b1);
        }
    }

    #pragma unroll
    for (int mt = 0; mt < 2; mt++) {
        int row = row0 + wid * 32 + mt * 16 + tg;
        #pragma unroll
        for (int half_i = 0; half_i < 2; half_i++) {
            int r = row + half_i * 8;
            if (r < N_NODES) {
                #pragma unroll
                for (int nt = 0; nt < 8; nt++) {
                    int col = nt * 8 + tig * 2;
                    *(__half2*)(g_y + (size_t)r * HD + col) =
                        __float22half2_rn(make_float2(c[mt][nt][half_i * 2 + 0],
                                                      c[mt][nt][half_i * 2 + 1]));
                }
            }
        }
    }
}

// ---------------- aggregation + BN + relu: FOUR nodes per warp, pipelined ------
// Software pipeline: next batch's csrsrc indices are loaded BEFORE the current
// batch's value loads are consumed; all 8 value loads issue back-to-back.
__global__ __launch_bounds__(256) void k_agg(const float* __restrict__ gam,
                                             const float* __restrict__ bet,
                                             const float* __restrict__ mea,
                                             const float* __restrict__ var) {
    __shared__ float sScale[64], sShift[64];
    int tid = threadIdx.x;
    if (tid < 64) {
        float sc = rsqrtf(var[tid] + BN_EPS) * gam[tid];
        sScale[tid] = sc;
        sShift[tid] = bet[tid] - mea[tid] * sc;
    }
    __syncthreads();

    int gw = (blockIdx.x * 256 + tid) >> 5;
    if (gw >= N_NODES / 4) return;
    int lane = tid & 31;
    int q = lane >> 3;
    int sub = lane & 7;
    int node = 4 * gw + q;
    int srcbase = q * 8;

    const uint4* yv = (const uint4*)g_y;

    float a[8];
    {
        uint4 raw = yv[(size_t)node * 8 + sub];
        float2 f0 = __half22float2(*(__half2*)&raw.x);
        float2 f1 = __half22float2(*(__half2*)&raw.y);
        float2 f2 = __half22float2(*(__half2*)&raw.z);
        float2 f3 = __half22float2(*(__half2*)&raw.w);
        a[0] = f0.x; a[1] = f0.y; a[2] = f1.x; a[3] = f1.y;
        a[4] = f2.x; a[5] = f2.y; a[6] = f3.x; a[7] = f3.y;
    }

    int b = g_rowptr[node];
    int end = g_rowptr[node + 1];
    int n = end - b;
    n = (n < 0) ? 0 : (n > 8 ? 8 : n);
    int idx = (sub < n) ? g_csrsrc[b + sub] : 0;

    while (__any_sync(0xffffffffu, b < end)) {
        // prefetch next batch's indices (hides csrsrc latency under value loads)
        int nb = b + 8;
        int n2 = end - nb;
        n2 = (n2 < 0) ? 0 : (n2 > 8 ? 8 : n2);
        int idx2 = (sub < n2) ? g_csrsrc[nb + sub] : 0;

        int s[8];
        #pragma unroll
        for (int t = 0; t < 8; t++)
            s[t] = __shfl_sync(0xffffffffu, idx, srcbase + t);

        uint4 r[8];
        #pragma unroll
        for (int t = 0; t < 8; t++)
            r[t] = yv[(size_t)s[t] * 8 + sub];

        #pragma unroll
        for (int t = 0; t < 8; t++) {
            if (t < n) {
                float2 u0 = __half22float2(*(__half2*)&r[t].x);
                float2 u1 = __half22float2(*(__half2*)&r[t].y);
                float2 u2 = __half22float2(*(__half2*)&r[t].z);
                float2 u3 = __half22float2(*(__half2*)&r[t].w);
                a[0] += u0.x; a[1] += u0.y; a[2] += u1.x; a[3] += u1.y;
                a[4] += u2.x; a[5] += u2.y; a[6] += u3.x; a[7] += u3.y;
            }
        }

        b = nb;
        n = n2;
        idx = idx2;
    }

    int c0 = sub * 8;
    float4 scA = *(float4*)&sScale[c0];
    float4 scB = *(float4*)&sScale[c0 + 4];
    float4 shA = *(float4*)&sShift[c0];
    float4 shB = *(float4*)&sShift[c0 + 4];
    float h0 = fmaxf(fmaf(a[0], scA.x, shA.x), 0.f);
    float h1 = fmaxf(fmaf(a[1], scA.y, shA.y), 0.f);
    float h2 = fmaxf(fmaf(a[2], scA.z, shA.z), 0.f);
    float h3 = fmaxf(fmaf(a[3], scA.w, shA.w), 0.f);
    float h4 = fmaxf(fmaf(a[4], scB.x, shB.x), 0.f);
    float h5 = fmaxf(fmaf(a[5], scB.y, shB.y), 0.f);
    float h6 = fmaxf(fmaf(a[6], scB.z, shB.z), 0.f);
    float h7 = fmaxf(fmaf(a[7], scB.w, shB.w), 0.f);
    uint4 outv;
    *(__half2*)&outv.x = __float22half2_rn(make_float2(h0, h1));
    *(__half2*)&outv.y = __float22half2_rn(make_float2(h2, h3));
    *(__half2*)&outv.z = __float22half2_rn(make_float2(h4, h5));
    *(__half2*)&outv.w = __float22half2_rn(make_float2(h6, h7));
    ((uint4*)g_a)[(size_t)node * 8 + sub] = outv;
}

// ---------------- final head (self-cleans g_pool / g_cnt) ----------------
__global__ void k_final(const float* __restrict__ lin1, const float* __restrict__ lin2,
                        const float* __restrict__ lb, float* __restrict__ out) {
    __shared__ float sL1[64 * 64];
    __shared__ float sL2[64 * 10];
    __shared__ float sB[10];
    int tid = threadIdx.x;
    for (int i = tid; i < 64 * 64; i += 128) sL1[i] = lin1[i];
    for (int i = tid; i < 64 * 10; i += 128) sL2[i] = lin2[i];
    if (tid < 10) sB[tid] = lb[tid];
    __syncthreads();
    if (tid < N_GRAPHS) {
        float cnt = (float)g_cnt[tid];
        if (cnt < 1.f) cnt = 1.f;
        float pooled[64];
        #pragma unroll
        for (int k = 0; k < 64; k++) {
            pooled[k] = g_pool[tid * 64 + k] / cnt;
            g_pool[tid * 64 + k] = 0.f;
        }
        g_cnt[tid] = 0;
        float o[10];
        #pragma unroll
        for (int c = 0; c < 10; c++) o[c] = sB[c];
        for (int j = 0; j < 64; j++) {
            float z = 0.f;
            #pragma unroll
            for (int k = 0; k < 64; k++) z += pooled[k] * sL1[k * 64 + j];
            z = fmaxf(z, 0.f);
            #pragma unroll
            for (int c = 0; c < 10; c++) o[c] += z * sL2[j * 10 + c];
        }
        float mx = o[0];
        #pragma unroll
        for (int c = 1; c < 10; c++) mx = fmaxf(mx, o[c]);
        float se = 0.f;
        #pragma unroll
        for (int c = 0; c < 10; c++) se += expf(o[c] - mx);
        float lse = logf(se) + mx;
        #pragma unroll
        for (int c = 0; c < 10; c++) out[tid * 10 + c] = o[c] - lse;
    }
}

// ---------------- launch ----------------
extern "C" void kernel_launch(void* const* d_in, const int* in_sizes, int n_in,
                              void* d_out, int out_size) {
    const float* x      = (const float*)d_in[0];
    const int*   ei     = (const int*)d_in[1];
    const int*   batch  = (const int*)d_in[2];
    const float* W1_0   = (const float*)d_in[3];
    const float* bn_g_0 = (const float*)d_in[4];
    const float* bn_b_0 = (const float*)d_in[5];
    const float* bn_m_0 = (const float*)d_in[6];
    const float* bn_v_0 = (const float*)d_in[7];
    const float* W2_0   = (const float*)d_in[8];
    const float* W1_r   = (const float*)d_in[9];
    const float* bn_g_r = (const float*)d_in[10];
    const float* bn_b_r = (const float*)d_in[11];
    const float* bn_m_r = (const float*)d_in[12];
    const float* bn_v_r = (const float*)d_in[13];
    const float* W2_r   = (const float*)d_in[14];
    const float* lin1   = (const float*)d_in[15];
    const float* lin2   = (const float*)d_in[16];
    const float* lin2b  = (const float*)d_in[17];
    float* out = (float*)d_out;

    const int TPB = 256;
    int gridEdges4 = (N_EDGES / 4 + TPB - 1) / TPB;      // 977
    int gridGemm0 = (N_NODES + 255) / 256;               // 391
    int gridDual = (N_NODES + 127) / 128;                // 782
    int gridAgg = ((N_NODES / 4) * 32 + TPB - 1) / TPB;  // 3125

    cudaStream_t side;
    cudaStreamCreateWithFlags(&side, cudaStreamNonBlocking);
    cudaEvent_t evFork, evJoin;
    cudaEventCreateWithFlags(&evFork, cudaEventDisableTiming);
    cudaEventCreateWithFlags(&evJoin, cudaEventDisableTiming);

    cudaEventRecord(evFork, 0);
    cudaStreamWaitEvent(side, evFork, 0);
    k_wprep<<<7, 256, 0, side>>>(W2_0, W1_r, W2_r);
    k_gemm0<<<gridGemm0, TPB, 0, side>>>(x, W1_0);      // y0 -> g_y
    cudaEventRecord(evJoin, side);

    k_count<<<gridEdges4, TPB>>>(ei, batch);
    k_scan1<<<SCAN_BLK, 1024>>>();
    k_scan23<<<SCAN_BLK, 1024>>>();
    k_scatter<<<gridEdges4, TPB>>>(ei);

    cudaStreamWaitEvent(0, evJoin, 0);

    k_agg<<<gridAgg, TPB>>>(bn_g_0, bn_b_0, bn_m_0, bn_v_0);
    k_dual<true><<<gridDual, 128>>>(0, 1, nullptr);
    k_agg<<<gridAgg, TPB>>>(bn_g_r + 0, bn_b_r + 0, bn_m_r + 0, bn_v_r + 0);
    k_dual<true><<<gridDual, 128>>>(2, 3, nullptr);
    k_agg<<<gridAgg, TPB>>>(bn_g_r + 64, bn_b_r + 64, bn_m_r + 64, bn_v_r + 64);
    k_dual<true><<<gridDual, 128>>>(4, 5, nullptr);
    k_agg<<<gridAgg, TPB>>>(bn_g_r + 128, bn_b_r + 128, bn_m_r + 128, bn_v_r + 128);
    k_dual<false><<<gridDual, 128>>>(6, 6, batch);

    k_final<<<1, 128>>>(lin1, lin2, lin2b, out);

    cudaStreamDestroy(side);
    cudaEventDestroy(evFork);
    cudaEventDestroy(evJoin);
}

// round 16
// speedup vs baseline: 1.3888x; 1.3888x over previous
#include <cuda_runtime.h>
#include <cuda_fp16.h>
#include <math.h>

#define N_NODES 100000
#define N_EDGES 1000000
#define N_GRAPHS 128
#define HD 64
#define BN_EPS 1e-5f

#define SCAN_BLK 25            // ceil(100000 / 4096)

// ---------------- scratch (device globals; no allocation allowed) ----------------
__device__ __align__(16) int    g_rowptr[N_NODES + 1];
__device__ __align__(16) int    g_cursor[N_NODES];
__device__ __align__(16) int    g_deg[N_NODES];
__device__ __align__(16) int    g_bsum[SCAN_BLK];
__device__ __align__(16) int    g_csrsrc[N_EDGES];
__device__ __align__(16) __half g_y[N_NODES * HD];
__device__ __align__(16) __half g_a[N_NODES * HD];
__device__ __align__(16) __half g_wt[7 * 4096];   // fp16 W^T [n][k], 7 matrices
__device__ __align__(16) float  g_pool[N_GRAPHS * HD];
__device__ __align__(16) int    g_cnt[N_GRAPHS];

// ---------------- helpers ----------------
__device__ __forceinline__ unsigned f2tf(float f) {
    unsigned u;
    asm("cvt.rna.tf32.f32 %0, %1;" : "=r"(u) : "f"(f));
    return u;
}
__device__ __forceinline__ void mma_tf32(float* c, const unsigned* a,
                                         unsigned b0, unsigned b1) {
    asm("mma.sync.aligned.m16n8k8.row.col.f32.tf32.tf32.f32 "
        "{%0,%1,%2,%3},{%4,%5,%6,%7},{%8,%9},{%0,%1,%2,%3};"
        : "+f"(c[0]), "+f"(c[1]), "+f"(c[2]), "+f"(c[3])
        : "r"(a[0]), "r"(a[1]), "r"(a[2]), "r"(a[3]), "r"(b0), "r"(b1));
}
__device__ __forceinline__ void mma_f16(float* c, const unsigned* a,
                                        unsigned b0, unsigned b1) {
    asm("mma.sync.aligned.m16n8k16.row.col.f32.f16.f16.f32 "
        "{%0,%1,%2,%3},{%4,%5,%6,%7},{%8,%9},{%0,%1,%2,%3};"
        : "+f"(c[0]), "+f"(c[1]), "+f"(c[2]), "+f"(c[3])
        : "r"(a[0]), "r"(a[1]), "r"(a[2]), "r"(a[3]), "r"(b0), "r"(b1));
}

// ---------------- weight prep: fp16 transposed copies (overlapped) ----------------
__global__ void k_wprep(const float* __restrict__ W2_0,
                        const float* __restrict__ W1_r,
                        const float* __restrict__ W2_r) {
    int b = blockIdx.x;
    const float* src = (b == 0) ? W2_0
                     : ((b & 1) ? W1_r + ((b - 1) / 2) * 4096
                                : W2_r + (b / 2 - 1) * 4096);
    __half* dst = g_wt + b * 4096;
    for (int i = threadIdx.x; i < 4096; i += 256) {
        int n = i >> 6, k = i & 63;
        dst[i] = __float2half(src[k * 64 + n]);
    }
}

// ---------------- CSR build ----------------
__global__ void k_count(const int* __restrict__ ei,
                        const int* __restrict__ batch) {
    int e = (blockIdx.x * blockDim.x + threadIdx.x) * 4;
    if (e < N_EDGES) {
        int4 d = *(const int4*)&ei[N_EDGES + e];
        atomicAdd(&g_deg[d.x], 1);
        atomicAdd(&g_deg[d.y], 1);
        atomicAdd(&g_deg[d.z], 1);
        atomicAdd(&g_deg[d.w], 1);
    }
    if (e < N_NODES) {
        int4 b = *(const int4*)&batch[e];
        atomicAdd(&g_cnt[b.x], 1);
        atomicAdd(&g_cnt[b.y], 1);
        atomicAdd(&g_cnt[b.z], 1);
        atomicAdd(&g_cnt[b.w], 1);
    }
}

__global__ __launch_bounds__(1024) void k_scan1() {
    __shared__ int warpsum[32];
    int tid = threadIdx.x, lane = tid & 31, wid = tid >> 5;
    int i0 = blockIdx.x * 4096 + tid * 4;
    int4 v = make_int4(0, 0, 0, 0);
    if (i0 + 3 < N_NODES) {
        v = *(const int4*)&g_deg[i0];
    } else {
        if (i0 + 0 < N_NODES) v.x = g_deg[i0 + 0];
        if (i0 + 1 < N_NODES) v.y = g_deg[i0 + 1];
        if (i0 + 2 < N_NODES) v.z = g_deg[i0 + 2];
        if (i0 + 3 < N_NODES) v.w = g_deg[i0 + 3];
    }
    int s = v.x + v.y + v.z + v.w;
    int x = s;
    #pragma unroll
    for (int off = 1; off < 32; off <<= 1) {
        int t = __shfl_up_sync(0xffffffffu, x, off);
        if (lane >= off) x += t;
    }
    if (lane == 31) warpsum[wid] = x;
    __syncthreads();
    if (wid == 0) {
        int w = warpsum[lane];
        #pragma unroll
        for (int off = 1; off < 32; off <<= 1) {
            int t = __shfl_up_sync(0xffffffffu, w, off);
            if (lane >= off) w += t;
        }
        warpsum[lane] = w;
    }
    __syncthreads();
    int woff = (wid > 0) ? warpsum[wid - 1] : 0;
    int excl = woff + (x - s);
    int p0 = excl + v.x, p1 = p0 + v.y, p2 = p1 + v.z;
    if (i0 + 0 < N_NODES) g_cursor[i0 + 0] = excl;
    if (i0 + 1 < N_NODES) g_cursor[i0 + 1] = p0;
    if (i0 + 2 < N_NODES) g_cursor[i0 + 2] = p1;
    if (i0 + 3 < N_NODES) g_cursor[i0 + 3] = p2;
    if (tid == 1023) g_bsum[blockIdx.x] = warpsum[31];
}

__global__ __launch_bounds__(1024) void k_scan23() {
    __shared__ int s_off;
    int tid = threadIdx.x;
    if (tid < 32) {
        int lane = tid;
        int v = (lane < SCAN_BLK) ? g_bsum[lane] : 0;
        int x = v;
        #pragma unroll
        for (int off = 1; off < 32; off <<= 1) {
            int t = __shfl_up_sync(0xffffffffu, x, off);
            if (lane >= off) x += t;
        }
        if (lane == blockIdx.x) s_off = x - v;
    }
    __syncthreads();
    int off = s_off;
    int i0 = blockIdx.x * 4096 + tid * 4;
    if (i0 + 3 < N_NODES) {
        int4 c = *(const int4*)&g_cursor[i0];
        c.x += off; c.y += off; c.z += off; c.w += off;
        *(int4*)&g_cursor[i0] = c;
        *(int4*)&g_rowptr[i0] = c;
        *(int4*)&g_deg[i0] = make_int4(0, 0, 0, 0);
    } else {
        #pragma unroll
        for (int j = 0; j < 4; j++) {
            if (i0 + j < N_NODES) {
                int c = g_cursor[i0 + j] + off;
                g_cursor[i0 + j] = c;
                g_rowptr[i0 + j] = c;
                g_deg[i0 + j] = 0;
            }
        }
    }
    if (blockIdx.x == 0 && tid == 0) g_rowptr[N_NODES] = N_EDGES;
}

__global__ void k_scatter(const int* __restrict__ ei) {
    int e = (blockIdx.x * blockDim.x + threadIdx.x) * 4;
    if (e >= N_EDGES) return;
    int4 d = *(const int4*)&ei[N_EDGES + e];
    int4 s = *(const int4*)&ei[e];
    int p0 = atomicAdd(&g_cursor[d.x], 1);
    int p1 = atomicAdd(&g_cursor[d.y], 1);
    int p2 = atomicAdd(&g_cursor[d.z], 1);
    int p3 = atomicAdd(&g_cursor[d.w], 1);
    g_csrsrc[p0] = s.x;
    g_csrsrc[p1] = s.y;
    g_csrsrc[p2] = s.z;
    g_csrsrc[p3] = s.w;
}

// ---------------- layer-0 input GEMM: g_y = x[N,128] @ W1_0[128,64] (TF32) ----
__global__ __launch_bounds__(256) void k_gemm0(const float* __restrict__ A,
                                               const float* __restrict__ W) {
    constexpr int K = 128;
    __shared__ unsigned sA[256 * 17];
    __shared__ unsigned sW[16 * 65];
    int tid = threadIdx.x;
    int wid = tid >> 5, lane = tid & 31;
    int tg = lane >> 2, tig = lane & 3;
    int row0 = blockIdx.x * 256;

    float c[2][8][4];
    #pragma unroll
    for (int mt = 0; mt < 2; mt++)
        #pragma unroll
        for (int nt = 0; nt < 8; nt++)
            #pragma unroll
            for (int j = 0; j < 4; j++) c[mt][nt][j] = 0.f;

    for (int ch = 0; ch < 8; ch++) {
        int kbase = ch * 16;
        #pragma unroll
        for (int i = 0; i < 4; i++) {
            int idx = tid + i * 256;
            int r = idx >> 2, c4 = idx & 3;
            int grow = row0 + r;
            float4 v = make_float4(0.f, 0.f, 0.f, 0.f);
            if (grow < N_NODES)
                v = *(const float4*)(A + (size_t)grow * K + kbase + c4 * 4);
            unsigned* p = &sA[r * 17 + c4 * 4];
            p[0] = f2tf(v.x); p[1] = f2tf(v.y); p[2] = f2tf(v.z); p[3] = f2tf(v.w);
        }
        {
            int k = tid >> 4, c4 = tid & 15;
            float4 v = *(const float4*)(W + (size_t)(kbase + k) * 64 + c4 * 4);
            unsigned* p = &sW[k * 65 + c4 * 4];
            p[0] = f2tf(v.x); p[1] = f2tf(v.y); p[2] = f2tf(v.z); p[3] = f2tf(v.w);
        }
        __syncthreads();
        #pragma unroll
        for (int ks = 0; ks < 2; ks++) {
            int ko = ks * 8;
            unsigned a[2][4];
            #pragma unroll
            for (int mt = 0; mt < 2; mt++) {
                int rr = wid * 32 + mt * 16 + tg;
                a[mt][0] = sA[rr * 17 + ko + tig];
                a[mt][1] = sA[(rr + 8) * 17 + ko + tig];
                a[mt][2] = sA[rr * 17 + ko + tig + 4];
                a[mt][3] = sA[(rr + 8) * 17 + ko + tig + 4];
            }
            #pragma unroll
            for (int nt = 0; nt < 8; nt++) {
                unsigned b0 = sW[(ko + tig) * 65 + nt * 8 + tg];
                unsigned b1 = sW[(ko + tig + 4) * 65 + nt * 8 + tg];
                mma_tf32(c[0][nt], a[0], b0, b1);
                mma_tf32(c[1][nt], a[1], b0, b1);
            }
        }
        __syncthreads();
    }
    #pragma unroll
    for (int mt = 0; mt < 2; mt++) {
        int row = row0 + wid * 32 + mt * 16 + tg;
        #pragma unroll
        for (int half_i = 0; half_i < 2; half_i++) {
            int r = row + half_i * 8;
            if (r < N_NODES) {
                #pragma unroll
                for (int nt = 0; nt < 8; nt++) {
                    int col = nt * 8 + tig * 2;
                    *(__half2*)(g_y + (size_t)r * HD + col) =
                        __float22half2_rn(make_float2(c[mt][nt][half_i * 2 + 0],
                                                      c[mt][nt][half_i * 2 + 1]));
                }
            }
        }
    }
}

// ---------------- chained dual GEMM, fp16 MMA, pre-transposed weights ----------
template <bool DUAL>
__global__ __launch_bounds__(128) void k_dual(int slot2, int slot1,
                                              const int* __restrict__ batch) {
    __shared__ __half sA[128 * 72];
    __shared__ __half sW2[64 * 72];
    __shared__ __half sW1[64 * 72];

    const __half* WT2 = g_wt + slot2 * 4096;
    const __half* WT1n = g_wt + slot1 * 4096;

    int tid = threadIdx.x, wid = tid >> 5, lane = tid & 31;
    int tg = lane >> 2, tig = lane & 3;
    int row0 = blockIdx.x * 128;

    #pragma unroll
    for (int i = 0; i < 8; i++) {
        int idx = tid + i * 128;
        int r = idx >> 3, seg = idx & 7;
        int grow = row0 + r;
        uint4 raw = make_uint4(0u, 0u, 0u, 0u);
        if (grow < N_NODES)
            raw = *(const uint4*)(g_a + (size_t)grow * HD + seg * 8);
        *(uint4*)&sA[r * 72 + seg * 8] = raw;
    }
    #pragma unroll
    for (int i = 0; i < 4; i++) {
        int idx = tid + i * 128;
        int r = idx >> 3, seg = idx & 7;
        *(uint4*)&sW2[r * 72 + seg * 8] = *(const uint4*)(WT2 + r * 64 + seg * 8);
        if (DUAL)
            *(uint4*)&sW1[r * 72 + seg * 8] = *(const uint4*)(WT1n + r * 64 + seg * 8);
    }
    __syncthreads();

    float c[2][8][4];
    #pragma unroll
    for (int mt = 0; mt < 2; mt++)
        #pragma unroll
        for (int nt = 0; nt < 8; nt++)
            #pragma unroll
            for (int j = 0; j < 4; j++) c[mt][nt][j] = 0.f;

    #pragma unroll
    for (int ks = 0; ks < 4; ks++) {
        int kg = ks * 16;
        unsigned a[2][4];
        #pragma unroll
        for (int mt = 0; mt < 2; mt++) {
            int rr = wid * 32 + mt * 16 + tg;
            a[mt][0] = *(unsigned*)&sA[rr * 72 + kg + 2 * tig];
            a[mt][1] = *(unsigned*)&sA[(rr + 8) * 72 + kg + 2 * tig];
            a[mt][2] = *(unsigned*)&sA[rr * 72 + kg + 2 * tig + 8];
            a[mt][3] = *(unsigned*)&sA[(rr + 8) * 72 + kg + 2 * tig + 8];
        }
        #pragma unroll
        for (int nt = 0; nt < 8; nt++) {
            unsigned b0 = *(unsigned*)&sW2[(nt * 8 + tg) * 72 + kg + 2 * tig];
            unsigned b1 = *(unsigned*)&sW2[(nt * 8 + tg) * 72 + kg + 2 * tig + 8];
            mma_f16(c[0][nt], a[0], b0, b1);
            mma_f16(c[1][nt], a[1], b0, b1);
        }
    }

    if (!DUAL) {
        #pragma unroll
        for (int mt = 0; mt < 2; mt++) {
            int row = row0 + wid * 32 + mt * 16 + tg;
            #pragma unroll
            for (int half_i = 0; half_i < 2; half_i++) {
                int r = row + half_i * 8;
                if (r < N_NODES) {
                    int b = batch[r];
                    #pragma unroll
                    for (int nt = 0; nt < 8; nt++) {
                        int col = nt * 8 + tig * 2;
                        atomicAdd(&g_pool[b * HD + col],
                                  fmaxf(c[mt][nt][half_i * 2 + 0], 0.f));
                        atomicAdd(&g_pool[b * HD + col + 1],
                                  fmaxf(c[mt][nt][half_i * 2 + 1], 0.f));
                    }
                }
            }
        }
        return;
    }

    #pragma unroll
    for (int mt = 0; mt < 2; mt++) {
        int rlo = wid * 32 + mt * 16 + tg;
        #pragma unroll
        for (int nt = 0; nt < 8; nt++) {
            int col = nt * 8 + 2 * tig;
            *(__half2*)&sA[rlo * 72 + col] =
                __float22half2_rn(make_float2(fmaxf(c[mt][nt][0], 0.f),
                                              fmaxf(c[mt][nt][1], 0.f)));
            *(__half2*)&sA[(rlo + 8) * 72 + col] =
                __float22half2_rn(make_float2(fmaxf(c[mt][nt][2], 0.f),
                                              fmaxf(c[mt][nt][3], 0.f)));
        }
    }
    __syncwarp();

    #pragma unroll
    for (int mt = 0; mt < 2; mt++)
        #pragma unroll
        for (int nt = 0; nt < 8; nt++)
            #pragma unroll
            for (int j = 0; j < 4; j++) c[mt][nt][j] = 0.f;

    #pragma unroll
    for (int ks = 0; ks < 4; ks++) {
        int kg = ks * 16;
        unsigned a[2][4];
        #pragma unroll
        for (int mt = 0; mt < 2; mt++) {
            int rr = wid * 32 + mt * 16 + tg;
            a[mt][0] = *(unsigned*)&sA[rr * 72 + kg + 2 * tig];
            a[mt][1] = *(unsigned*)&sA[(rr + 8) * 72 + kg + 2 * tig];
            a[mt][2] = *(unsigned*)&sA[rr * 72 + kg + 2 * tig + 8];
            a[mt][3] = *(unsigned*)&sA[(rr + 8) * 72 + kg + 2 * tig + 8];
        }
        #pragma unroll
        for (int nt = 0; nt < 8; nt++) {
            unsigned b0 = *(unsigned*)&sW1[(nt * 8 + tg) * 72 + kg + 2 * tig];
            unsigned b1 = *(unsigned*)&sW1[(nt * 8 + tg) * 72 + kg + 2 * tig + 8];
            mma_f16(c[0][nt], a[0], b0, b1);
            mma_f16(c[1][nt], a[1], b0, b1);
        }
    }

    #pragma unroll
    for (int mt = 0; mt < 2; mt++) {
        int row = row0 + wid * 32 + mt * 16 + tg;
        #pragma unroll
        for (int half_i = 0; half_i < 2; half_i++) {
            int r = row + half_i * 8;
            if (r < N_NODES) {
                #pragma unroll
                for (int nt = 0; nt < 8; nt++) {
                    int col = nt * 8 + tig * 2;
                    *(__half2*)(g_y + (size_t)r * HD + col) =
                        __float22half2_rn(make_float2(c[mt][nt][half_i * 2 + 0],
                                                      c[mt][nt][half_i * 2 + 1]));
                }
            }
        }
    }
}

// ---------------- aggregation + BN + relu: FOUR nodes per warp ----------------
// R14 structure (warp-max bounded 4-wide chunks) + prefetch of next batch's idx.
__global__ __launch_bounds__(256) void k_agg(const float* __restrict__ gam,
                                             const float* __restrict__ bet,
                                             const float* __restrict__ mea,
                                             const float* __restrict__ var) {
    __shared__ float sScale[64], sShift[64];
    int tid = threadIdx.x;
    if (tid < 64) {
        float sc = rsqrtf(var[tid] + BN_EPS) * gam[tid];
        sScale[tid] = sc;
        sShift[tid] = bet[tid] - mea[tid] * sc;
    }
    __syncthreads();

    int gw = (blockIdx.x * 256 + tid) >> 5;
    if (gw >= N_NODES / 4) return;
    int lane = tid & 31;
    int q = lane >> 3;
    int sub = lane & 7;
    int node = 4 * gw + q;
    int srcbase = q * 8;

    const uint4* yv = (const uint4*)g_y;

    float a[8];
    {
        uint4 raw = yv[(size_t)node * 8 + sub];
        float2 f0 = __half22float2(*(__half2*)&raw.x);
        float2 f1 = __half22float2(*(__half2*)&raw.y);
        float2 f2 = __half22float2(*(__half2*)&raw.z);
        float2 f3 = __half22float2(*(__half2*)&raw.w);
        a[0] = f0.x; a[1] = f0.y; a[2] = f1.x; a[3] = f1.y;
        a[4] = f2.x; a[5] = f2.y; a[6] = f3.x; a[7] = f3.y;
    }

    int b = g_rowptr[node];
    int end = g_rowptr[node + 1];
    int n = end - b;
    n = (n < 0) ? 0 : (n > 8 ? 8 : n);
    int idx = (sub < n) ? g_csrsrc[b + sub] : 0;

    while (__any_sync(0xffffffffu, b < end)) {
        // prefetch next batch's indices (hides csrsrc latency under value loads)
        int nb = b + 8;
        int n2 = end - nb;
        n2 = (n2 < 0) ? 0 : (n2 > 8 ? 8 : n2);
        int idx2 = (sub < n2) ? g_csrsrc[nb + sub] : 0;

        // warp-max active count bounds load issue (R14 discipline)
        int m = n;
        m = max(m, __shfl_xor_sync(0xffffffffu, m, 8));
        m = max(m, __shfl_xor_sync(0xffffffffu, m, 16));

        int t = 0;
        for (; t + 4 <= m; t += 4) {
            int s0 = __shfl_sync(0xffffffffu, idx, srcbase + t + 0);
            int s1 = __shfl_sync(0xffffffffu, idx, srcbase + t + 1);
            int s2 = __shfl_sync(0xffffffffu, idx, srcbase + t + 2);
            int s3 = __shfl_sync(0xffffffffu, idx, srcbase + t + 3);
            uint4 r0 = yv[(size_t)s0 * 8 + sub];
            uint4 r1 = yv[(size_t)s1 * 8 + sub];
            uint4 r2 = yv[(size_t)s2 * 8 + sub];
            uint4 r3 = yv[(size_t)s3 * 8 + sub];
            if (t + 0 < n) {
                float2 u0 = __half22float2(*(__half2*)&r0.x);
                float2 u1 = __half22float2(*(__half2*)&r0.y);
                float2 u2 = __half22float2(*(__half2*)&r0.z);
                float2 u3 = __half22float2(*(__half2*)&r0.w);
                a[0] += u0.x; a[1] += u0.y; a[2] += u1.x; a[3] += u1.y;
                a[4] += u2.x; a[5] += u2.y; a[6] += u3.x; a[7] += u3.y;
            }
            if (t + 1 < n) {
                float2 u0 = __half22float2(*(__half2*)&r1.x);
                float2 u1 = __half22float2(*(__half2*)&r1.y);
                float2 u2 = __half22float2(*(__half2*)&r1.z);
                float2 u3 = __half22float2(*(__half2*)&r1.w);
                a[0] += u0.x; a[1] += u0.y; a[2] += u1.x; a[3] += u1.y;
                a[4] += u2.x; a[5] += u2.y; a[6] += u3.x; a[7] += u3.y;
            }
            if (t + 2 < n) {
                float2 u0 = __half22float2(*(__half2*)&r2.x);
                float2 u1 = __half22float2(*(__half2*)&r2.y);
                float2 u2 = __half22float2(*(__half2*)&r2.z);
                float2 u3 = __half22float2(*(__half2*)&r2.w);
                a[0] += u0.x; a[1] += u0.y; a[2] += u1.x; a[3] += u1.y;
                a[4] += u2.x; a[5] += u2.y; a[6] += u3.x; a[7] += u3.y;
            }
            if (t + 3 < n) {
                float2 u0 = __half22float2(*(__half2*)&r3.x);
                float2 u1 = __half22float2(*(__half2*)&r3.y);
                float2 u2 = __half22float2(*(__half2*)&r3.z);
                float2 u3 = __half22float2(*(__half2*)&r3.w);
                a[0] += u0.x; a[1] += u0.y; a[2] += u1.x; a[3] += u1.y;
                a[4] += u2.x; a[5] += u2.y; a[6] += u3.x; a[7] += u3.y;
            }
        }
        for (; t < m; t++) {
            int s = __shfl_sync(0xffffffffu, idx, srcbase + t);
            uint4 r = yv[(size_t)s * 8 + sub];
            if (t < n) {
                float2 u0 = __half22float2(*(__half2*)&r.x);
                float2 u1 = __half22float2(*(__half2*)&r.y);
                float2 u2 = __half22float2(*(__half2*)&r.z);
                float2 u3 = __half22float2(*(__half2*)&r.w);
                a[0] += u0.x; a[1] += u0.y; a[2] += u1.x; a[3] += u1.y;
                a[4] += u2.x; a[5] += u2.y; a[6] += u3.x; a[7] += u3.y;
            }
        }

        b = nb;
        n = n2;
        idx = idx2;
    }

    int c0 = sub * 8;
    float4 scA = *(float4*)&sScale[c0];
    float4 scB = *(float4*)&sScale[c0 + 4];
    float4 shA = *(float4*)&sShift[c0];
    float4 shB = *(float4*)&sShift[c0 + 4];
    float h0 = fmaxf(fmaf(a[0], scA.x, shA.x), 0.f);
    float h1 = fmaxf(fmaf(a[1], scA.y, shA.y), 0.f);
    float h2 = fmaxf(fmaf(a[2], scA.z, shA.z), 0.f);
    float h3 = fmaxf(fmaf(a[3], scA.w, shA.w), 0.f);
    float h4 = fmaxf(fmaf(a[4], scB.x, shB.x), 0.f);
    float h5 = fmaxf(fmaf(a[5], scB.y, shB.y), 0.f);
    float h6 = fmaxf(fmaf(a[6], scB.z, shB.z), 0.f);
    float h7 = fmaxf(fmaf(a[7], scB.w, shB.w), 0.f);
    uint4 outv;
    *(__half2*)&outv.x = __float22half2_rn(make_float2(h0, h1));
    *(__half2*)&outv.y = __float22half2_rn(make_float2(h2, h3));
    *(__half2*)&outv.z = __float22half2_rn(make_float2(h4, h5));
    *(__half2*)&outv.w = __float22half2_rn(make_float2(h6, h7));
    ((uint4*)g_a)[(size_t)node * 8 + sub] = outv;
}

// ---------------- final head (self-cleans g_pool / g_cnt) ----------------
__global__ void k_final(const float* __restrict__ lin1, const float* __restrict__ lin2,
                        const float* __restrict__ lb, float* __restrict__ out) {
    __shared__ float sL1[64 * 64];
    __shared__ float sL2[64 * 10];
    __shared__ float sB[10];
    int tid = threadIdx.x;
    for (int i = tid; i < 64 * 64; i += 128) sL1[i] = lin1[i];
    for (int i = tid; i < 64 * 10; i += 128) sL2[i] = lin2[i];
    if (tid < 10) sB[tid] = lb[tid];
    __syncthreads();
    if (tid < N_GRAPHS) {
        float cnt = (float)g_cnt[tid];
        if (cnt < 1.f) cnt = 1.f;
        float pooled[64];
        #pragma unroll
        for (int k = 0; k < 64; k++) {
            pooled[k] = g_pool[tid * 64 + k] / cnt;
            g_pool[tid * 64 + k] = 0.f;
        }
        g_cnt[tid] = 0;
        float o[10];
        #pragma unroll
        for (int c = 0; c < 10; c++) o[c] = sB[c];
        for (int j = 0; j < 64; j++) {
            float z = 0.f;
            #pragma unroll
            for (int k = 0; k < 64; k++) z += pooled[k] * sL1[k * 64 + j];
            z = fmaxf(z, 0.f);
            #pragma unroll
            for (int c = 0; c < 10; c++) o[c] += z * sL2[j * 10 + c];
        }
        float mx = o[0];
        #pragma unroll
        for (int c = 1; c < 10; c++) mx = fmaxf(mx, o[c]);
        float se = 0.f;
        #pragma unroll
        for (int c = 0; c < 10; c++) se += expf(o[c] - mx);
        float lse = logf(se) + mx;
        #pragma unroll
        for (int c = 0; c < 10; c++) out[tid * 10 + c] = o[c] - lse;
    }
}

// ---------------- launch ----------------
extern "C" void kernel_launch(void* const* d_in, const int* in_sizes, int n_in,
                              void* d_out, int out_size) {
    const float* x      = (const float*)d_in[0];
    const int*   ei     = (const int*)d_in[1];
    const int*   batch  = (const int*)d_in[2];
    const float* W1_0   = (const float*)d_in[3];
    const float* bn_g_0 = (const float*)d_in[4];
    const float* bn_b_0 = (const float*)d_in[5];
    const float* bn_m_0 = (const float*)d_in[6];
    const float* bn_v_0 = (const float*)d_in[7];
    const float* W2_0   = (const float*)d_in[8];
    const float* W1_r   = (const float*)d_in[9];
    const float* bn_g_r = (const float*)d_in[10];
    const float* bn_b_r = (const float*)d_in[11];
    const float* bn_m_r = (const float*)d_in[12];
    const float* bn_v_r = (const float*)d_in[13];
    const float* W2_r   = (const float*)d_in[14];
    const float* lin1   = (const float*)d_in[15];
    const float* lin2   = (const float*)d_in[16];
    const float* lin2b  = (const float*)d_in[17];
    float* out = (float*)d_out;

    const int TPB = 256;
    int gridEdges4 = (N_EDGES / 4 + TPB - 1) / TPB;      // 977
    int gridGemm0 = (N_NODES + 255) / 256;               // 391
    int gridDual = (N_NODES + 127) / 128;                // 782
    int gridAgg = ((N_NODES / 4) * 32 + TPB - 1) / TPB;  // 3125

    cudaStream_t side;
    cudaStreamCreateWithFlags(&side, cudaStreamNonBlocking);
    cudaEvent_t evFork, evJoin;
    cudaEventCreateWithFlags(&evFork, cudaEventDisableTiming);
    cudaEventCreateWithFlags(&evJoin, cudaEventDisableTiming);

    cudaEventRecord(evFork, 0);
    cudaStreamWaitEvent(side, evFork, 0);
    k_wprep<<<7, 256, 0, side>>>(W2_0, W1_r, W2_r);
    k_gemm0<<<gridGemm0, TPB, 0, side>>>(x, W1_0);      // y0 -> g_y
    cudaEventRecord(evJoin, side);

    k_count<<<gridEdges4, TPB>>>(ei, batch);
    k_scan1<<<SCAN_BLK, 1024>>>();
    k_scan23<<<SCAN_BLK, 1024>>>();
    k_scatter<<<gridEdges4, TPB>>>(ei);

    cudaStreamWaitEvent(0, evJoin, 0);

    k_agg<<<gridAgg, TPB>>>(bn_g_0, bn_b_0, bn_m_0, bn_v_0);
    k_dual<true><<<gridDual, 128>>>(0, 1, nullptr);
    k_agg<<<gridAgg, TPB>>>(bn_g_r + 0, bn_b_r + 0, bn_m_r + 0, bn_v_r + 0);
    k_dual<true><<<gridDual, 128>>>(2, 3, nullptr);
    k_agg<<<gridAgg, TPB>>>(bn_g_r + 64, bn_b_r + 64, bn_m_r + 64, bn_v_r + 64);
    k_dual<true><<<gridDual, 128>>>(4, 5, nullptr);
    k_agg<<<gridAgg, TPB>>>(bn_g_r + 128, bn_b_r + 128, bn_m_r + 128, bn_v_r + 128);
    k_dual<false><<<gridDual, 128>>>(6, 6, batch);

    k_final<<<1, 128>>>(lin1, lin2, lin2b, out);

    cudaStreamDestroy(side);
    cudaEventDestroy(evFork);
    cudaEventDestroy(evJoin);
}

// round 17
// speedup vs baseline: 1.4203x; 1.0227x over previous
#include <cuda_runtime.h>
#include <cuda_fp16.h>
#include <math.h>

#define N_NODES 100000
#define N_EDGES 1000000
#define N_GRAPHS 128
#define HD 64
#define BN_EPS 1e-5f

#define SCAN_BLK 25            // ceil(100000 / 4096)

// ---------------- scratch (device globals; no allocation allowed) ----------------
__device__ __align__(16) int    g_rowptr[N_NODES + 1];
__device__ __align__(16) int    g_cursor[N_NODES];
__device__ __align__(16) int    g_deg[N_NODES];
__device__ __align__(16) int    g_bsum[SCAN_BLK];
__device__ __align__(16) int    g_csrsrc[N_EDGES];
__device__ __align__(16) __half g_y[N_NODES * HD];
__device__ __align__(16) __half g_a[N_NODES * HD];
__device__ __align__(16) __half g_wt[7 * 4096];   // fp16 W^T [n][k], 7 matrices
__device__ __align__(16) float  g_pool[N_GRAPHS * HD];
__device__ __align__(16) int    g_cnt[N_GRAPHS];

// ---------------- helpers ----------------
__device__ __forceinline__ unsigned f2tf(float f) {
    unsigned u;
    asm("cvt.rna.tf32.f32 %0, %1;" : "=r"(u) : "f"(f));
    return u;
}
__device__ __forceinline__ void mma_tf32(float* c, const unsigned* a,
                                         unsigned b0, unsigned b1) {
    asm("mma.sync.aligned.m16n8k8.row.col.f32.tf32.tf32.f32 "
        "{%0,%1,%2,%3},{%4,%5,%6,%7},{%8,%9},{%0,%1,%2,%3};"
        : "+f"(c[0]), "+f"(c[1]), "+f"(c[2]), "+f"(c[3])
        : "r"(a[0]), "r"(a[1]), "r"(a[2]), "r"(a[3]), "r"(b0), "r"(b1));
}
__device__ __forceinline__ void mma_f16(float* c, const unsigned* a,
                                        unsigned b0, unsigned b1) {
    asm("mma.sync.aligned.m16n8k16.row.col.f32.f16.f16.f32 "
        "{%0,%1,%2,%3},{%4,%5,%6,%7},{%8,%9},{%0,%1,%2,%3};"
        : "+f"(c[0]), "+f"(c[1]), "+f"(c[2]), "+f"(c[3])
        : "r"(a[0]), "r"(a[1]), "r"(a[2]), "r"(a[3]), "r"(b0), "r"(b1));
}

// ---------------- weight prep: fp16 transposed copies (overlapped) ----------------
__global__ void k_wprep(const float* __restrict__ W2_0,
                        const float* __restrict__ W1_r,
                        const float* __restrict__ W2_r) {
    int b = blockIdx.x;
    const float* src = (b == 0) ? W2_0
                     : ((b & 1) ? W1_r + ((b - 1) / 2) * 4096
                                : W2_r + (b / 2 - 1) * 4096);
    __half* dst = g_wt + b * 4096;
    for (int i = threadIdx.x; i < 4096; i += 256) {
        int n = i >> 6, k = i & 63;
        dst[i] = __float2half(src[k * 64 + n]);
    }
}

// ---------------- CSR build: 8 edges per thread ----------------
__global__ void k_count(const int* __restrict__ ei,
                        const int* __restrict__ batch) {
    int e = (blockIdx.x * blockDim.x + threadIdx.x) * 8;
    if (e < N_EDGES) {
        int4 d0 = *(const int4*)&ei[N_EDGES + e];
        int4 d1 = *(const int4*)&ei[N_EDGES + e + 4];
        atomicAdd(&g_deg[d0.x], 1);
        atomicAdd(&g_deg[d0.y], 1);
        atomicAdd(&g_deg[d0.z], 1);
        atomicAdd(&g_deg[d0.w], 1);
        atomicAdd(&g_deg[d1.x], 1);
        atomicAdd(&g_deg[d1.y], 1);
        atomicAdd(&g_deg[d1.z], 1);
        atomicAdd(&g_deg[d1.w], 1);
    }
    if (e < N_NODES) {
        int4 b0 = *(const int4*)&batch[e];
        int4 b1 = *(const int4*)&batch[e + 4];
        atomicAdd(&g_cnt[b0.x], 1);
        atomicAdd(&g_cnt[b0.y], 1);
        atomicAdd(&g_cnt[b0.z], 1);
        atomicAdd(&g_cnt[b0.w], 1);
        atomicAdd(&g_cnt[b1.x], 1);
        atomicAdd(&g_cnt[b1.y], 1);
        atomicAdd(&g_cnt[b1.z], 1);
        atomicAdd(&g_cnt[b1.w], 1);
    }
}

__global__ __launch_bounds__(1024) void k_scan1() {
    __shared__ int warpsum[32];
    int tid = threadIdx.x, lane = tid & 31, wid = tid >> 5;
    int i0 = blockIdx.x * 4096 + tid * 4;
    int4 v = make_int4(0, 0, 0, 0);
    if (i0 + 3 < N_NODES) {
        v = *(const int4*)&g_deg[i0];
    } else {
        if (i0 + 0 < N_NODES) v.x = g_deg[i0 + 0];
        if (i0 + 1 < N_NODES) v.y = g_deg[i0 + 1];
        if (i0 + 2 < N_NODES) v.z = g_deg[i0 + 2];
        if (i0 + 3 < N_NODES) v.w = g_deg[i0 + 3];
    }
    int s = v.x + v.y + v.z + v.w;
    int x = s;
    #pragma unroll
    for (int off = 1; off < 32; off <<= 1) {
        int t = __shfl_up_sync(0xffffffffu, x, off);
        if (lane >= off) x += t;
    }
    if (lane == 31) warpsum[wid] = x;
    __syncthreads();
    if (wid == 0) {
        int w = warpsum[lane];
        #pragma unroll
        for (int off = 1; off < 32; off <<= 1) {
            int t = __shfl_up_sync(0xffffffffu, w, off);
            if (lane >= off) w += t;
        }
        warpsum[lane] = w;
    }
    __syncthreads();
    int woff = (wid > 0) ? warpsum[wid - 1] : 0;
    int excl = woff + (x - s);
    int p0 = excl + v.x, p1 = p0 + v.y, p2 = p1 + v.z;
    if (i0 + 0 < N_NODES) g_cursor[i0 + 0] = excl;
    if (i0 + 1 < N_NODES) g_cursor[i0 + 1] = p0;
    if (i0 + 2 < N_NODES) g_cursor[i0 + 2] = p1;
    if (i0 + 3 < N_NODES) g_cursor[i0 + 3] = p2;
    if (tid == 1023) g_bsum[blockIdx.x] = warpsum[31];
}

__global__ __launch_bounds__(1024) void k_scan23() {
    __shared__ int s_off;
    int tid = threadIdx.x;
    if (tid < 32) {
        int lane = tid;
        int v = (lane < SCAN_BLK) ? g_bsum[lane] : 0;
        int x = v;
        #pragma unroll
        for (int off = 1; off < 32; off <<= 1) {
            int t = __shfl_up_sync(0xffffffffu, x, off);
            if (lane >= off) x += t;
        }
        if (lane == blockIdx.x) s_off = x - v;
    }
    __syncthreads();
    int off = s_off;
    int i0 = blockIdx.x * 4096 + tid * 4;
    if (i0 + 3 < N_NODES) {
        int4 c = *(const int4*)&g_cursor[i0];
        c.x += off; c.y += off; c.z += off; c.w += off;
        *(int4*)&g_cursor[i0] = c;
        *(int4*)&g_rowptr[i0] = c;
        *(int4*)&g_deg[i0] = make_int4(0, 0, 0, 0);
    } else {
        #pragma unroll
        for (int j = 0; j < 4; j++) {
            if (i0 + j < N_NODES) {
                int c = g_cursor[i0 + j] + off;
                g_cursor[i0 + j] = c;
                g_rowptr[i0 + j] = c;
                g_deg[i0 + j] = 0;
            }
        }
    }
    if (blockIdx.x == 0 && tid == 0) g_rowptr[N_NODES] = N_EDGES;
}

__global__ void k_scatter(const int* __restrict__ ei) {
    int e = (blockIdx.x * blockDim.x + threadIdx.x) * 8;
    if (e >= N_EDGES) return;
    int4 d0 = *(const int4*)&ei[N_EDGES + e];
    int4 d1 = *(const int4*)&ei[N_EDGES + e + 4];
    int4 s0 = *(const int4*)&ei[e];
    int4 s1 = *(const int4*)&ei[e + 4];
    int p0 = atomicAdd(&g_cursor[d0.x], 1);
    int p1 = atomicAdd(&g_cursor[d0.y], 1);
    int p2 = atomicAdd(&g_cursor[d0.z], 1);
    int p3 = atomicAdd(&g_cursor[d0.w], 1);
    int p4 = atomicAdd(&g_cursor[d1.x], 1);
    int p5 = atomicAdd(&g_cursor[d1.y], 1);
    int p6 = atomicAdd(&g_cursor[d1.z], 1);
    int p7 = atomicAdd(&g_cursor[d1.w], 1);
    g_csrsrc[p0] = s0.x;
    g_csrsrc[p1] = s0.y;
    g_csrsrc[p2] = s0.z;
    g_csrsrc[p3] = s0.w;
    g_csrsrc[p4] = s1.x;
    g_csrsrc[p5] = s1.y;
    g_csrsrc[p6] = s1.z;
    g_csrsrc[p7] = s1.w;
}

// ---------------- layer-0 input GEMM: g_y = x[N,128] @ W1_0[128,64] (TF32) ----
__global__ __launch_bounds__(256) void k_gemm0(const float* __restrict__ A,
                                               const float* __restrict__ W) {
    constexpr int K = 128;
    __shared__ unsigned sA[256 * 17];
    __shared__ unsigned sW[16 * 65];
    int tid = threadIdx.x;
    int wid = tid >> 5, lane = tid & 31;
    int tg = lane >> 2, tig = lane & 3;
    int row0 = blockIdx.x * 256;

    float c[2][8][4];
    #pragma unroll
    for (int mt = 0; mt < 2; mt++)
        #pragma unroll
        for (int nt = 0; nt < 8; nt++)
            #pragma unroll
            for (int j = 0; j < 4; j++) c[mt][nt][j] = 0.f;

    for (int ch = 0; ch < 8; ch++) {
        int kbase = ch * 16;
        #pragma unroll
        for (int i = 0; i < 4; i++) {
            int idx = tid + i * 256;
            int r = idx >> 2, c4 = idx & 3;
            int grow = row0 + r;
            float4 v = make_float4(0.f, 0.f, 0.f, 0.f);
            if (grow < N_NODES)
                v = *(const float4*)(A + (size_t)grow * K + kbase + c4 * 4);
            unsigned* p = &sA[r * 17 + c4 * 4];
            p[0] = f2tf(v.x); p[1] = f2tf(v.y); p[2] = f2tf(v.z); p[3] = f2tf(v.w);
        }
        {
            int k = tid >> 4, c4 = tid & 15;
            float4 v = *(const float4*)(W + (size_t)(kbase + k) * 64 + c4 * 4);
            unsigned* p = &sW[k * 65 + c4 * 4];
            p[0] = f2tf(v.x); p[1] = f2tf(v.y); p[2] = f2tf(v.z); p[3] = f2tf(v.w);
        }
        __syncthreads();
        #pragma unroll
        for (int ks = 0; ks < 2; ks++) {
            int ko = ks * 8;
            unsigned a[2][4];
            #pragma unroll
            for (int mt = 0; mt < 2; mt++) {
                int rr = wid * 32 + mt * 16 + tg;
                a[mt][0] = sA[rr * 17 + ko + tig];
                a[mt][1] = sA[(rr + 8) * 17 + ko + tig];
                a[mt][2] = sA[rr * 17 + ko + tig + 4];
                a[mt][3] = sA[(rr + 8) * 17 + ko + tig + 4];
            }
            #pragma unroll
            for (int nt = 0; nt < 8; nt++) {
                unsigned b0 = sW[(ko + tig) * 65 + nt * 8 + tg];
                unsigned b1 = sW[(ko + tig + 4) * 65 + nt * 8 + tg];
                mma_tf32(c[0][nt], a[0], b0, b1);
                mma_tf32(c[1][nt], a[1], b0, b1);
            }
        }
        __syncthreads();
    }
    #pragma unroll
    for (int mt = 0; mt < 2; mt++) {
        int row = row0 + wid * 32 + mt * 16 + tg;
        #pragma unroll
        for (int half_i = 0; half_i < 2; half_i++) {
            int r = row + half_i * 8;
            if (r < N_NODES) {
                #pragma unroll
                for (int nt = 0; nt < 8; nt++) {
                    int col = nt * 8 + tig * 2;
                    *(__half2*)(g_y + (size_t)r * HD + col) =
                        __float22half2_rn(make_float2(c[mt][nt][half_i * 2 + 0],
                                                      c[mt][nt][half_i * 2 + 1]));
                }
            }
        }
    }
}

// ---------------- chained dual GEMM, fp16 MMA, pre-transposed weights ----------
template <bool DUAL>
__global__ __launch_bounds__(128) void k_dual(int slot2, int slot1,
                                              const int* __restrict__ batch) {
    __shared__ __half sA[128 * 72];
    __shared__ __half sW2[64 * 72];
    __shared__ __half sW1[64 * 72];

    const __half* WT2 = g_wt + slot2 * 4096;
    const __half* WT1n = g_wt + slot1 * 4096;

    int tid = threadIdx.x, wid = tid >> 5, lane = tid & 31;
    int tg = lane >> 2, tig = lane & 3;
    int row0 = blockIdx.x * 128;

    #pragma unroll
    for (int i = 0; i < 8; i++) {
        int idx = tid + i * 128;
        int r = idx >> 3, seg = idx & 7;
        int grow = row0 + r;
        uint4 raw = make_uint4(0u, 0u, 0u, 0u);
        if (grow < N_NODES)
            raw = *(const uint4*)(g_a + (size_t)grow * HD + seg * 8);
        *(uint4*)&sA[r * 72 + seg * 8] = raw;
    }
    #pragma unroll
    for (int i = 0; i < 4; i++) {
        int idx = tid + i * 128;
        int r = idx >> 3, seg = idx & 7;
        *(uint4*)&sW2[r * 72 + seg * 8] = *(const uint4*)(WT2 + r * 64 + seg * 8);
        if (DUAL)
            *(uint4*)&sW1[r * 72 + seg * 8] = *(const uint4*)(WT1n + r * 64 + seg * 8);
    }
    __syncthreads();

    float c[2][8][4];
    #pragma unroll
    for (int mt = 0; mt < 2; mt++)
        #pragma unroll
        for (int nt = 0; nt < 8; nt++)
            #pragma unroll
            for (int j = 0; j < 4; j++) c[mt][nt][j] = 0.f;

    #pragma unroll
    for (int ks = 0; ks < 4; ks++) {
        int kg = ks * 16;
        unsigned a[2][4];
        #pragma unroll
        for (int mt = 0; mt < 2; mt++) {
            int rr = wid * 32 + mt * 16 + tg;
            a[mt][0] = *(unsigned*)&sA[rr * 72 + kg + 2 * tig];
            a[mt][1] = *(unsigned*)&sA[(rr + 8) * 72 + kg + 2 * tig];
            a[mt][2] = *(unsigned*)&sA[rr * 72 + kg + 2 * tig + 8];
            a[mt][3] = *(unsigned*)&sA[(rr + 8) * 72 + kg + 2 * tig + 8];
        }
        #pragma unroll
        for (int nt = 0; nt < 8; nt++) {
            unsigned b0 = *(unsigned*)&sW2[(nt * 8 + tg) * 72 + kg + 2 * tig];
            unsigned b1 = *(unsigned*)&sW2[(nt * 8 + tg) * 72 + kg + 2 * tig + 8];
            mma_f16(c[0][nt], a[0], b0, b1);
            mma_f16(c[1][nt], a[1], b0, b1);
        }
    }

    if (!DUAL) {
        #pragma unroll
        for (int mt = 0; mt < 2; mt++) {
            int row = row0 + wid * 32 + mt * 16 + tg;
            #pragma unroll
            for (int half_i = 0; half_i < 2; half_i++) {
                int r = row + half_i * 8;
                if (r < N_NODES) {
                    int b = batch[r];
                    #pragma unroll
                    for (int nt = 0; nt < 8; nt++) {
                        int col = nt * 8 + tig * 2;
                        atomicAdd(&g_pool[b * HD + col],
                                  fmaxf(c[mt][nt][half_i * 2 + 0], 0.f));
                        atomicAdd(&g_pool[b * HD + col + 1],
                                  fmaxf(c[mt][nt][half_i * 2 + 1], 0.f));
                    }
                }
            }
        }
        return;
    }

    #pragma unroll
    for (int mt = 0; mt < 2; mt++) {
        int rlo = wid * 32 + mt * 16 + tg;
        #pragma unroll
        for (int nt = 0; nt < 8; nt++) {
            int col = nt * 8 + 2 * tig;
            *(__half2*)&sA[rlo * 72 + col] =
                __float22half2_rn(make_float2(fmaxf(c[mt][nt][0], 0.f),
                                              fmaxf(c[mt][nt][1], 0.f)));
            *(__half2*)&sA[(rlo + 8) * 72 + col] =
                __float22half2_rn(make_float2(fmaxf(c[mt][nt][2], 0.f),
                                              fmaxf(c[mt][nt][3], 0.f)));
        }
    }
    __syncwarp();

    #pragma unroll
    for (int mt = 0; mt < 2; mt++)
        #pragma unroll
        for (int nt = 0; nt < 8; nt++)
            #pragma unroll
            for (int j = 0; j < 4; j++) c[mt][nt][j] = 0.f;

    #pragma unroll
    for (int ks = 0; ks < 4; ks++) {
        int kg = ks * 16;
        unsigned a[2][4];
        #pragma unroll
        for (int mt = 0; mt < 2; mt++) {
            int rr = wid * 32 + mt * 16 + tg;
            a[mt][0] = *(unsigned*)&sA[rr * 72 + kg + 2 * tig];
            a[mt][1] = *(unsigned*)&sA[(rr + 8) * 72 + kg + 2 * tig];
            a[mt][2] = *(unsigned*)&sA[rr * 72 + kg + 2 * tig + 8];
            a[mt][3] = *(unsigned*)&sA[(rr + 8) * 72 + kg + 2 * tig + 8];
        }
        #pragma unroll
        for (int nt = 0; nt < 8; nt++) {
            unsigned b0 = *(unsigned*)&sW1[(nt * 8 + tg) * 72 + kg + 2 * tig];
            unsigned b1 = *(unsigned*)&sW1[(nt * 8 + tg) * 72 + kg + 2 * tig + 8];
            mma_f16(c[0][nt], a[0], b0, b1);
            mma_f16(c[1][nt], a[1], b0, b1);
        }
    }

    #pragma unroll
    for (int mt = 0; mt < 2; mt++) {
        int row = row0 + wid * 32 + mt * 16 + tg;
        #pragma unroll
        for (int half_i = 0; half_i < 2; half_i++) {
            int r = row + half_i * 8;
            if (r < N_NODES) {
                #pragma unroll
                for (int nt = 0; nt < 8; nt++) {
                    int col = nt * 8 + tig * 2;
                    *(__half2*)(g_y + (size_t)r * HD + col) =
                        __float22half2_rn(make_float2(c[mt][nt][half_i * 2 + 0],
                                                      c[mt][nt][half_i * 2 + 1]));
                }
            }
        }
    }
}

// ---------------- aggregation + BN + relu: FOUR nodes per warp (R14 exact) -----
__global__ __launch_bounds__(256) void k_agg(const float* __restrict__ gam,
                                             const float* __restrict__ bet,
                                             const float* __restrict__ mea,
                                             const float* __restrict__ var) {
    __shared__ float sScale[64], sShift[64];
    int tid = threadIdx.x;
    if (tid < 64) {
        float sc = rsqrtf(var[tid] + BN_EPS) * gam[tid];
        sScale[tid] = sc;
        sShift[tid] = bet[tid] - mea[tid] * sc;
    }
    __syncthreads();

    int gw = (blockIdx.x * 256 + tid) >> 5;
    if (gw >= N_NODES / 4) return;
    int lane = tid & 31;
    int q = lane >> 3;
    int sub = lane & 7;
    int node = 4 * gw + q;

    const uint4* yv = (const uint4*)g_y;

    float a[8];
    {
        uint4 raw = yv[(size_t)node * 8 + sub];
        float2 f0 = __half22float2(*(__half2*)&raw.x);
        float2 f1 = __half22float2(*(__half2*)&raw.y);
        float2 f2 = __half22float2(*(__half2*)&raw.z);
        float2 f3 = __half22float2(*(__half2*)&raw.w);
        a[0] = f0.x; a[1] = f0.y; a[2] = f1.x; a[3] = f1.y;
        a[4] = f2.x; a[5] = f2.y; a[6] = f3.x; a[7] = f3.y;
    }

    int b = g_rowptr[node];
    int end = g_rowptr[node + 1];

    while (__any_sync(0xffffffffu, b < end)) {
        int n = end - b;
        if (n > 8) n = 8;
        if (n < 0) n = 0;
        int idx = (sub < n) ? g_csrsrc[b + sub] : 0;
        int m = n;
        m = max(m, __shfl_xor_sync(0xffffffffu, m, 8));
        m = max(m, __shfl_xor_sync(0xffffffffu, m, 16));
        int srcbase = q * 8;
        int t = 0;
        for (; t + 4 <= m; t += 4) {
            int s0 = __shfl_sync(0xffffffffu, idx, srcbase + t + 0);
            int s1 = __shfl_sync(0xffffffffu, idx, srcbase + t + 1);
            int s2 = __shfl_sync(0xffffffffu, idx, srcbase + t + 2);
            int s3 = __shfl_sync(0xffffffffu, idx, srcbase + t + 3);
            uint4 r0 = yv[(size_t)s0 * 8 + sub];
            uint4 r1 = yv[(size_t)s1 * 8 + sub];
            uint4 r2 = yv[(size_t)s2 * 8 + sub];
            uint4 r3 = yv[(size_t)s3 * 8 + sub];
            if (t + 0 < n) {
                float2 u0 = __half22float2(*(__half2*)&r0.x);
                float2 u1 = __half22float2(*(__half2*)&r0.y);
                float2 u2 = __half22float2(*(__half2*)&r0.z);
                float2 u3 = __half22float2(*(__half2*)&r0.w);
                a[0] += u0.x; a[1] += u0.y; a[2] += u1.x; a[3] += u1.y;
                a[4] += u2.x; a[5] += u2.y; a[6] += u3.x; a[7] += u3.y;
            }
            if (t + 1 < n) {
                float2 u0 = __half22float2(*(__half2*)&r1.x);
                float2 u1 = __half22float2(*(__half2*)&r1.y);
                float2 u2 = __half22float2(*(__half2*)&r1.z);
                float2 u3 = __half22float2(*(__half2*)&r1.w);
                a[0] += u0.x; a[1] += u0.y; a[2] += u1.x; a[3] += u1.y;
                a[4] += u2.x; a[5] += u2.y; a[6] += u3.x; a[7] += u3.y;
            }
            if (t + 2 < n) {
                float2 u0 = __half22float2(*(__half2*)&r2.x);
                float2 u1 = __half22float2(*(__half2*)&r2.y);
                float2 u2 = __half22float2(*(__half2*)&r2.z);
                float2 u3 = __half22float2(*(__half2*)&r2.w);
                a[0] += u0.x; a[1] += u0.y; a[2] += u1.x; a[3] += u1.y;
                a[4] += u2.x; a[5] += u2.y; a[6] += u3.x; a[7] += u3.y;
            }
            if (t + 3 < n) {
                float2 u0 = __half22float2(*(__half2*)&r3.x);
                float2 u1 = __half22float2(*(__half2*)&r3.y);
                float2 u2 = __half22float2(*(__half2*)&r3.z);
                float2 u3 = __half22float2(*(__half2*)&r3.w);
                a[0] += u0.x; a[1] += u0.y; a[2] += u1.x; a[3] += u1.y;
                a[4] += u2.x; a[5] += u2.y; a[6] += u3.x; a[7] += u3.y;
            }
        }
        for (; t < m; t++) {
            int s = __shfl_sync(0xffffffffu, idx, srcbase + t);
            uint4 r = yv[(size_t)s * 8 + sub];
            if (t < n) {
                float2 u0 = __half22float2(*(__half2*)&r.x);
                float2 u1 = __half22float2(*(__half2*)&r.y);
                float2 u2 = __half22float2(*(__half2*)&r.z);
                float2 u3 = __half22float2(*(__half2*)&r.w);
                a[0] += u0.x; a[1] += u0.y; a[2] += u1.x; a[3] += u1.y;
                a[4] += u2.x; a[5] += u2.y; a[6] += u3.x; a[7] += u3.y;
            }
        }
        b += 8;
    }

    int c0 = sub * 8;
    float4 scA = *(float4*)&sScale[c0];
    float4 scB = *(float4*)&sScale[c0 + 4];
    float4 shA = *(float4*)&sShift[c0];
    float4 shB = *(float4*)&sShift[c0 + 4];
    float h0 = fmaxf(fmaf(a[0], scA.x, shA.x), 0.f);
    float h1 = fmaxf(fmaf(a[1], scA.y, shA.y), 0.f);
    float h2 = fmaxf(fmaf(a[2], scA.z, shA.z), 0.f);
    float h3 = fmaxf(fmaf(a[3], scA.w, shA.w), 0.f);
    float h4 = fmaxf(fmaf(a[4], scB.x, shB.x), 0.f);
    float h5 = fmaxf(fmaf(a[5], scB.y, shB.y), 0.f);
    float h6 = fmaxf(fmaf(a[6], scB.z, shB.z), 0.f);
    float h7 = fmaxf(fmaf(a[7], scB.w, shB.w), 0.f);
    uint4 outv;
    *(__half2*)&outv.x = __float22half2_rn(make_float2(h0, h1));
    *(__half2*)&outv.y = __float22half2_rn(make_float2(h2, h3));
    *(__half2*)&outv.z = __float22half2_rn(make_float2(h4, h5));
    *(__half2*)&outv.w = __float22half2_rn(make_float2(h6, h7));
    ((uint4*)g_a)[(size_t)node * 8 + sub] = outv;
}

// ---------------- final head (self-cleans g_pool / g_cnt) ----------------
__global__ void k_final(const float* __restrict__ lin1, const float* __restrict__ lin2,
                        const float* __restrict__ lb, float* __restrict__ out) {
    __shared__ float sL1[64 * 64];
    __shared__ float sL2[64 * 10];
    __shared__ float sB[10];
    int tid = threadIdx.x;
    for (int i = tid; i < 64 * 64; i += 128) sL1[i] = lin1[i];
    for (int i = tid; i < 64 * 10; i += 128) sL2[i] = lin2[i];
    if (tid < 10) sB[tid] = lb[tid];
    __syncthreads();
    if (tid < N_GRAPHS) {
        float cnt = (float)g_cnt[tid];
        if (cnt < 1.f) cnt = 1.f;
        float pooled[64];
        #pragma unroll
        for (int k = 0; k < 64; k++) {
            pooled[k] = g_pool[tid * 64 + k] / cnt;
            g_pool[tid * 64 + k] = 0.f;
        }
        g_cnt[tid] = 0;
        float o[10];
        #pragma unroll
        for (int c = 0; c < 10; c++) o[c] = sB[c];
        for (int j = 0; j < 64; j++) {
            float z = 0.f;
            #pragma unroll
            for (int k = 0; k < 64; k++) z += pooled[k] * sL1[k * 64 + j];
            z = fmaxf(z, 0.f);
            #pragma unroll
            for (int c = 0; c < 10; c++) o[c] += z * sL2[j * 10 + c];
        }
        float mx = o[0];
        #pragma unroll
        for (int c = 1; c < 10; c++) mx = fmaxf(mx, o[c]);
        float se = 0.f;
        #pragma unroll
        for (int c = 0; c < 10; c++) se += expf(o[c] - mx);
        float lse = logf(se) + mx;
        #pragma unroll
        for (int c = 0; c < 10; c++) out[tid * 10 + c] = o[c] - lse;
    }
}

// ---------------- launch ----------------
extern "C" void kernel_launch(void* const* d_in, const int* in_sizes, int n_in,
                              void* d_out, int out_size) {
    const float* x      = (const float*)d_in[0];
    const int*   ei     = (const int*)d_in[1];
    const int*   batch  = (const int*)d_in[2];
    const float* W1_0   = (const float*)d_in[3];
    const float* bn_g_0 = (const float*)d_in[4];
    const float* bn_b_0 = (const float*)d_in[5];
    const float* bn_m_0 = (const float*)d_in[6];
    const float* bn_v_0 = (const float*)d_in[7];
    const float* W2_0   = (const float*)d_in[8];
    const float* W1_r   = (const float*)d_in[9];
    const float* bn_g_r = (const float*)d_in[10];
    const float* bn_b_r = (const float*)d_in[11];
    const float* bn_m_r = (const float*)d_in[12];
    const float* bn_v_r = (const float*)d_in[13];
    const float* W2_r   = (const float*)d_in[14];
    const float* lin1   = (const float*)d_in[15];
    const float* lin2   = (const float*)d_in[16];
    const float* lin2b  = (const float*)d_in[17];
    float* out = (float*)d_out;

    const int TPB = 256;
    int gridEdges8 = (N_EDGES / 8 + TPB - 1) / TPB;      // 489
    int gridGemm0 = (N_NODES + 255) / 256;               // 391
    int gridDual = (N_NODES + 127) / 128;                // 782
    int gridAgg = ((N_NODES / 4) * 32 + TPB - 1) / TPB;  // 3125

    cudaStream_t side;
    cudaStreamCreateWithFlags(&side, cudaStreamNonBlocking);
    cudaEvent_t evFork, evJoin;
    cudaEventCreateWithFlags(&evFork, cudaEventDisableTiming);
    cudaEventCreateWithFlags(&evJoin, cudaEventDisableTiming);

    cudaEventRecord(evFork, 0);
    cudaStreamWaitEvent(side, evFork, 0);
    k_wprep<<<7, 256, 0, side>>>(W2_0, W1_r, W2_r);
    k_gemm0<<<gridGemm0, TPB, 0, side>>>(x, W1_0);      // y0 -> g_y
    cudaEventRecord(evJoin, side);

    k_count<<<gridEdges8, TPB>>>(ei, batch);
    k_scan1<<<SCAN_BLK, 1024>>>();
    k_scan23<<<SCAN_BLK, 1024>>>();
    k_scatter<<<gridEdges8, TPB>>>(ei);

    cudaStreamWaitEvent(0, evJoin, 0);

    k_agg<<<gridAgg, TPB>>>(bn_g_0, bn_b_0, bn_m_0, bn_v_0);
    k_dual<true><<<gridDual, 128>>>(0, 1, nullptr);
    k_agg<<<gridAgg, TPB>>>(bn_g_r + 0, bn_b_r + 0, bn_m_r + 0, bn_v_r + 0);
    k_dual<true><<<gridDual, 128>>>(2, 3, nullptr);
    k_agg<<<gridAgg, TPB>>>(bn_g_r + 64, bn_b_r + 64, bn_m_r + 64, bn_v_r + 64);
    k_dual<true><<<gridDual, 128>>>(4, 5, nullptr);
    k_agg<<<gridAgg, TPB>>>(bn_g_r + 128, bn_b_r + 128, bn_m_r + 128, bn_v_r + 128);
    k_dual<false><<<gridDual, 128>>>(6, 6, batch);

    k_final<<<1, 128>>>(lin1, lin2, lin2b, out);

    cudaStreamDestroy(side);
    cudaEventDestroy(evFork);
    cudaEventDestroy(evJoin);
}